// round 5
// baseline (speedup 1.0000x reference)
#include <cuda_runtime.h>

// ---------------- scratch (__device__ globals; no allocation allowed) ----------------
__device__ float g_scale[4];                 // gx/||Vx||, gy/.., gz/.., gh/..
__device__ float g_hx[8*32*256];
__device__ float g_hy[8*32*256];
__device__ float g_hz[8*32*256];
__device__ float g_attraw[8*2*32768];        // pre-softmax logits [b][h][x][y][z]
__device__ float g_partmax[8*2*32];          // per (b,h,x) block max
__device__ float g_M[16];                    // softmax max per (b,h)
__device__ float g_inv[16];                  // 1/sumexp per (b,h)
__device__ float g_attsum[8*32768];          // sum over h of softmaxed att
__device__ float g_part[8*32*256];           // per (b,x) logits partials

// ---------------- K0: weight-norm scales ----------------
__global__ void k_scales(const float* Vx, const float* gx,
                         const float* Vy, const float* gy,
                         const float* Vz, const float* gz,
                         const float* Vh, const float* gh) {
    __shared__ float red[256];
    int j = blockIdx.x;
    const float* V; const float* g; int n;
    if (j == 0)      { V = Vx; g = gx; n = 32768; }
    else if (j == 1) { V = Vy; g = gy; n = 32768; }
    else if (j == 2) { V = Vz; g = gz; n = 32768; }
    else             { V = Vh; g = gh; n = 512;   }
    float ss = 0.f;
    for (int i = threadIdx.x; i < n; i += 256) { float v = V[i]; ss += v * v; }
    red[threadIdx.x] = ss; __syncthreads();
    for (int s = 128; s > 0; s >>= 1) {
        if (threadIdx.x < s) red[threadIdx.x] += red[threadIdx.x + s];
        __syncthreads();
    }
    if (threadIdx.x == 0) g_scale[j] = g[0] / sqrtf(red[0]);
}

// ---------------- K1: projections  h = relu(in @ (scale*V)^T + b) ----------------
// grid (4 k-quads, 8 b, 3 mats), 256 threads. Thread = (k-col within quad, row-group of 8).
__global__ void __launch_bounds__(256) k_proj(
    const float* __restrict__ xin, const float* __restrict__ yin, const float* __restrict__ zin,
    const float* __restrict__ Vx, const float* __restrict__ bx,
    const float* __restrict__ Vy, const float* __restrict__ by,
    const float* __restrict__ Vz, const float* __restrict__ bz) {
    __shared__ float sIn[32*128];
    __shared__ float sV[64*33];
    int q = blockIdx.x, b = blockIdx.y, m = blockIdx.z;
    const float* in   = (m == 0) ? xin : (m == 1) ? yin : zin;
    const float* V    = (m == 0) ? Vx  : (m == 1) ? Vy  : Vz;
    const float* bias = (m == 0) ? bx  : (m == 1) ? by  : bz;
    float* out        = (m == 0) ? g_hx : (m == 1) ? g_hy : g_hz;
    int tid = threadIdx.x;
    int k0 = q * 64;
    for (int e = tid; e < 4096; e += 256) sIn[e] = in[b * 4096 + e];
    int kk = tid & 63, rg = tid >> 6, r0 = rg * 8;
    float acc[8] = {0,0,0,0,0,0,0,0};
    for (int dc = 0; dc < 128; dc += 32) {
        __syncthreads();
        for (int e = tid; e < 2048; e += 256) {
            int kr = e >> 5, d = e & 31;
            sV[kr * 33 + d] = V[(k0 + kr) * 128 + dc + d];
        }
        __syncthreads();
        for (int d = 0; d < 32; d += 4) {
            float v0 = sV[kk*33 + d], v1 = sV[kk*33 + d + 1];
            float v2 = sV[kk*33 + d + 2], v3 = sV[kk*33 + d + 3];
            #pragma unroll
            for (int r = 0; r < 8; r++) {
                float4 iv = *(const float4*)&sIn[(r0 + r) * 128 + dc + d];
                acc[r] += iv.x * v0 + iv.y * v1 + iv.z * v2 + iv.w * v3;
            }
        }
    }
    float scale = g_scale[m];
    float bb = bias[k0 + kk];
    #pragma unroll
    for (int r = 0; r < 8; r++) {
        float v = acc[r] * scale + bb;
        out[(b * 32 + r0 + r) * 256 + k0 + kk] = v > 0.f ? v : 0.f;
    }
}

// ---------------- K2: att GEMM  att[b,h,x,y,z] = Σ_k (hx*hy)[y,k] * (hz*Wh)[zh,k] + bh ----------------
// grid (32 x, 8 b), 128 threads, 4y x 4zh register tile. Also emits per-(b,h,x) max.
__global__ void __launch_bounds__(128) k_att(const float* __restrict__ Vh,
                                             const float* __restrict__ bhp) {
    __shared__ float st[32*64];    // t[y][kc], phase-broadcast reads
    __shared__ float sw[64*68];    // w[kc][zh], padded -> contiguous 128B per phase
    __shared__ float red[128];
    int x = blockIdx.x, b = blockIdx.y;
    int tid = threadIdx.x;
    int yg = tid >> 4, zg = tid & 15;
    float scaleH = g_scale[3];
    float4 acc[4];
    acc[0] = acc[1] = acc[2] = acc[3] = make_float4(0.f, 0.f, 0.f, 0.f);
    const float* hx  = g_hx + (b * 32 + x) * 256;
    const float* hyB = g_hy + b * 8192;
    const float* hzB = g_hz + b * 8192;
    for (int c = 0; c < 4; c++) {
        int k0 = c * 64;
        __syncthreads();
        for (int e = tid; e < 2048; e += 128) {
            int kc = e & 63, y = e >> 6;
            st[y * 64 + kc] = hx[k0 + kc] * hyB[y * 256 + k0 + kc];
        }
        for (int e = tid; e < 4096; e += 128) {
            int kc = e & 63, zh = e >> 6;
            sw[kc * 68 + zh] = hzB[(zh >> 1) * 256 + k0 + kc] *
                               Vh[(zh & 1) * 256 + k0 + kc] * scaleH;
        }
        __syncthreads();
        #pragma unroll 4
        for (int kc = 0; kc < 64; kc++) {
            float4 w = *(const float4*)&sw[kc * 68 + zg * 4];
            float t0 = st[(yg*4 + 0) * 64 + kc];
            float t1 = st[(yg*4 + 1) * 64 + kc];
            float t2 = st[(yg*4 + 2) * 64 + kc];
            float t3 = st[(yg*4 + 3) * 64 + kc];
            acc[0].x += t0*w.x; acc[0].y += t0*w.y; acc[0].z += t0*w.z; acc[0].w += t0*w.w;
            acc[1].x += t1*w.x; acc[1].y += t1*w.y; acc[1].z += t1*w.z; acc[1].w += t1*w.w;
            acc[2].x += t2*w.x; acc[2].y += t2*w.y; acc[2].z += t2*w.z; acc[2].w += t2*w.w;
            acc[3].x += t3*w.x; acc[3].y += t3*w.y; acc[3].z += t3*w.z; acc[3].w += t3*w.w;
        }
    }
    float b0 = bhp[0], b1 = bhp[1];
    float m0 = -1e30f, m1 = -1e30f;
    float* r0base = g_attraw + ((b * 2 + 0) * 32 + x) * 1024;
    float* r1base = g_attraw + ((b * 2 + 1) * 32 + x) * 1024;
    int z0 = zg * 2;
    #pragma unroll
    for (int i = 0; i < 4; i++) {
        int y = yg * 4 + i;
        float4 v = acc[i];
        v.x += b0; v.y += b1; v.z += b0; v.w += b1;
        m0 = fmaxf(m0, fmaxf(v.x, v.z));
        m1 = fmaxf(m1, fmaxf(v.y, v.w));
        r0base[y * 32 + z0]     = v.x;   // (h=0, z=z0)
        r1base[y * 32 + z0]     = v.y;   // (h=1, z=z0)
        r0base[y * 32 + z0 + 1] = v.z;   // (h=0, z=z0+1)
        r1base[y * 32 + z0 + 1] = v.w;   // (h=1, z=z0+1)
    }
    red[tid] = m0; __syncthreads();
    for (int s = 64; s > 0; s >>= 1) { if (tid < s) red[tid] = fmaxf(red[tid], red[tid + s]); __syncthreads(); }
    float M0 = red[0]; __syncthreads();
    red[tid] = m1; __syncthreads();
    for (int s = 64; s > 0; s >>= 1) { if (tid < s) red[tid] = fmaxf(red[tid], red[tid + s]); __syncthreads(); }
    if (tid == 0) {
        g_partmax[(b * 2 + 0) * 32 + x] = M0;
        g_partmax[(b * 2 + 1) * 32 + x] = red[0];
    }
}

// ---------------- K3: softmax reduce (max + sumexp per (b,h)) ----------------
__global__ void __launch_bounds__(512) k_soft1() {
    __shared__ float red[512];
    int bh = blockIdx.x, tid = threadIdx.x;
    float m = (tid < 32) ? g_partmax[bh * 32 + tid] : -1e30f;
    red[tid] = m; __syncthreads();
    for (int s = 256; s > 0; s >>= 1) { if (tid < s) red[tid] = fmaxf(red[tid], red[tid + s]); __syncthreads(); }
    float M = red[0];
    __syncthreads();
    const float* raw = g_attraw + bh * 32768;
    float s = 0.f;
    for (int i = tid; i < 32768; i += 512) s += expf(raw[i] - M);
    red[tid] = s; __syncthreads();
    for (int st = 256; st > 0; st >>= 1) { if (tid < st) red[tid] += red[tid + st]; __syncthreads(); }
    if (tid == 0) { g_M[bh] = M; g_inv[bh] = 1.f / red[0]; }
}

// ---------------- K4: finalize att (write to output) + att_sum over heads ----------------
__global__ void k_soft2(float* __restrict__ att_out) {
    int id = blockIdx.x * 256 + threadIdx.x;   // 262144 total
    int b = id >> 15, i = id & 32767;
    float M0 = g_M[b*2],   I0 = g_inv[b*2];
    float M1 = g_M[b*2+1], I1 = g_inv[b*2+1];
    float a0 = expf(g_attraw[(b*2 + 0) * 32768 + i] - M0) * I0;
    float a1 = expf(g_attraw[(b*2 + 1) * 32768 + i] - M1) * I1;
    att_out[(b*2 + 0) * 32768 + i] = a0;
    att_out[(b*2 + 1) * 32768 + i] = a1;
    g_attsum[b * 32768 + i] = a0 + a1;
}

// ---------------- K5: logits partials  part[b,x,k] = Σ_y t[y,k] * (Σ_z attsum[y,z]*hz[z,k]) ----------------
// grid (32 x, 8 b), 256 threads (one k each). hz staged transposed [k][z] (pad 36).
__global__ void __launch_bounds__(256) k_logit() {
    __shared__ float sa[1024];
    __shared__ float shz[256*36];
    int x = blockIdx.x, b = blockIdx.y, tid = threadIdx.x;
    for (int e = tid; e < 1024; e += 256) sa[e] = g_attsum[b * 32768 + x * 1024 + e];
    for (int e = tid; e < 8192; e += 256) {
        int k = e & 255, z = e >> 8;
        shz[k * 36 + z] = g_hz[(b * 32 + z) * 256 + k];
    }
    __syncthreads();
    float sxk = g_hx[(b * 32 + x) * 256 + tid];
    const float* hyB = g_hy + b * 8192;
    float acc = 0.f;
    for (int y = 0; y < 32; y++) {
        float s = 0.f;
        #pragma unroll
        for (int z = 0; z < 32; z += 4) {
            float4 a4 = *(const float4*)&sa[y * 32 + z];
            float4 h4 = *(const float4*)&shz[tid * 36 + z];
            s += a4.x*h4.x + a4.y*h4.y + a4.z*h4.z + a4.w*h4.w;
        }
        acc += sxk * hyB[y * 256 + tid] * s;
    }
    g_part[(b * 32 + x) * 256 + tid] = acc;
}

// ---------------- K6: reduce partials over x + BatchNorm over batch (fused) ----------------
__global__ void __launch_bounds__(256) k_bn(const float* __restrict__ gamma,
                                            const float* __restrict__ beta,
                                            float* __restrict__ outp) {
    int k = threadIdx.x;
    float l[8];
    float mean = 0.f;
    #pragma unroll
    for (int b = 0; b < 8; b++) {
        float s = 0.f;
        #pragma unroll 8
        for (int x = 0; x < 32; x++) s += g_part[(b * 32 + x) * 256 + k];
        l[b] = s;
        mean += s;
    }
    mean *= 0.125f;
    float var = 0.f;
    #pragma unroll
    for (int b = 0; b < 8; b++) { float d = l[b] - mean; var += d * d; }
    var *= 0.125f;
    float sc = gamma[k] / sqrtf(var + 1e-5f);
    float bt = beta[k];
    #pragma unroll
    for (int b = 0; b < 8; b++) outp[b * 256 + k] = (l[b] - mean) * sc + bt;
}

// ---------------- launch ----------------
extern "C" void kernel_launch(void* const* d_in, const int* in_sizes, int n_in,
                              void* d_out, int out_size) {
    const float* x     = (const float*)d_in[0];
    const float* y     = (const float*)d_in[1];
    const float* z     = (const float*)d_in[2];
    const float* Vx    = (const float*)d_in[3];
    const float* gx    = (const float*)d_in[4];
    const float* bx    = (const float*)d_in[5];
    const float* Vy    = (const float*)d_in[6];
    const float* gy    = (const float*)d_in[7];
    const float* by    = (const float*)d_in[8];
    const float* Vz    = (const float*)d_in[9];
    const float* gz    = (const float*)d_in[10];
    const float* bz    = (const float*)d_in[11];
    const float* Vh    = (const float*)d_in[12];
    const float* gh    = (const float*)d_in[13];
    const float* bh    = (const float*)d_in[14];
    const float* gamma = (const float*)d_in[15];
    const float* beta  = (const float*)d_in[16];

    float* out     = (float*)d_out;          // [8,256]
    float* att_out = out + 2048;             // [8,2,32,32,32]

    k_scales<<<4, 256>>>(Vx, gx, Vy, gy, Vz, gz, Vh, gh);
    k_proj  <<<dim3(4, 8, 3), 256>>>(x, y, z, Vx, bx, Vy, by, Vz, bz);
    k_att   <<<dim3(32, 8), 128>>>(Vh, bh);
    k_soft1 <<<16, 512>>>();
    k_soft2 <<<1024, 256>>>(att_out);
    k_logit <<<dim3(32, 8), 256>>>();
    k_bn    <<<1, 256>>>(gamma, beta, out);
}

// round 6
// speedup vs baseline: 1.1818x; 1.1818x over previous
#include <cuda_runtime.h>

// ---------------- scratch (__device__ globals; no allocation allowed) ----------------
__device__ float g_hx[8*32*256];
__device__ float g_hy[8*32*256];
__device__ float g_hz[8*32*256];
__device__ float g_attraw[8*2*32768];        // pre-softmax logits [b][h][x][y][z]
__device__ float g_partmax[8*2*32];          // per (b,h,x) block max
__device__ float g_partsum[8*2*32];          // per (b,h,x) Σexp(v - localmax)
__device__ float g_part[8*32*256];           // per (b,x) logits partials

// ---------------- K1: projections  h = relu(in @ (g/||V|| * V)^T + b) ----------------
// grid (4 k-quads, 8 b, 3 mats), 256 threads. Norm of V computed redundantly per block
// (primes L2 for the GEMM reads; removes the separate k_scales kernel).
__global__ void __launch_bounds__(256) k_proj(
    const float* __restrict__ xin, const float* __restrict__ yin, const float* __restrict__ zin,
    const float* __restrict__ Vx, const float* __restrict__ gx, const float* __restrict__ bx,
    const float* __restrict__ Vy, const float* __restrict__ gy, const float* __restrict__ by,
    const float* __restrict__ Vz, const float* __restrict__ gz, const float* __restrict__ bz) {
    __shared__ float sIn[32*128];
    __shared__ float sV[64*33];
    __shared__ float red[256];
    int q = blockIdx.x, b = blockIdx.y, m = blockIdx.z;
    const float* in   = (m == 0) ? xin : (m == 1) ? yin : zin;
    const float* V    = (m == 0) ? Vx  : (m == 1) ? Vy  : Vz;
    const float* gp   = (m == 0) ? gx  : (m == 1) ? gy  : gz;
    const float* bias = (m == 0) ? bx  : (m == 1) ? by  : bz;
    float* out        = (m == 0) ? g_hx : (m == 1) ? g_hy : g_hz;
    int tid = threadIdx.x;
    int k0 = q * 64;

    // stage input tile + compute ||V||^2 (redundant per block, L2-hot)
    for (int e = tid; e < 4096; e += 256) sIn[e] = in[b * 4096 + e];
    float ss = 0.f;
    for (int i = tid; i < 32768; i += 256) { float v = V[i]; ss += v * v; }
    red[tid] = ss; __syncthreads();
    for (int s = 128; s > 0; s >>= 1) {
        if (tid < s) red[tid] += red[tid + s];
        __syncthreads();
    }
    float scale = gp[0] / sqrtf(red[0]);

    int kk = tid & 63, rg = tid >> 6, r0 = rg * 8;
    float acc[8] = {0,0,0,0,0,0,0,0};
    for (int dc = 0; dc < 128; dc += 32) {
        __syncthreads();
        for (int e = tid; e < 2048; e += 256) {
            int kr = e >> 5, d = e & 31;
            sV[kr * 33 + d] = V[(k0 + kr) * 128 + dc + d];
        }
        __syncthreads();
        for (int d = 0; d < 32; d += 4) {
            float v0 = sV[kk*33 + d], v1 = sV[kk*33 + d + 1];
            float v2 = sV[kk*33 + d + 2], v3 = sV[kk*33 + d + 3];
            #pragma unroll
            for (int r = 0; r < 8; r++) {
                float4 iv = *(const float4*)&sIn[(r0 + r) * 128 + dc + d];
                acc[r] += iv.x * v0 + iv.y * v1 + iv.z * v2 + iv.w * v3;
            }
        }
    }
    float bb = bias[k0 + kk];
    #pragma unroll
    for (int r = 0; r < 8; r++) {
        float v = acc[r] * scale + bb;
        out[(b * 32 + r0 + r) * 256 + k0 + kk] = v > 0.f ? v : 0.f;
    }
}

// ---------------- K2: att GEMM + per-(b,h,x) softmax partials ----------------
// att[b,h,x,y,z] = Σ_k (hx*hy)[y,k] * (hz*Wh)[zh,k] + bh
// grid (32 x, 8 b), 128 threads, 4y x 4zh register tile.
// Emits raw att, block max M_x AND block Σexp(v−M_x)  (online-softmax partials).
__global__ void __launch_bounds__(128) k_att(const float* __restrict__ Vh,
                                             const float* __restrict__ ghp,
                                             const float* __restrict__ bhp) {
    __shared__ float st[32*64];    // t[y][kc], phase-broadcast reads
    __shared__ float sw[64*68];    // w[kc][zh], padded -> contiguous 128B per phase
    __shared__ float red[128];
    int x = blockIdx.x, b = blockIdx.y;
    int tid = threadIdx.x;
    int yg = tid >> 4, zg = tid & 15;

    // ||Vh|| (512 elements) — redundant per block, trivial
    float ssh = 0.f;
    for (int i = tid; i < 512; i += 128) { float v = Vh[i]; ssh += v * v; }
    red[tid] = ssh; __syncthreads();
    for (int s = 64; s > 0; s >>= 1) { if (tid < s) red[tid] += red[tid + s]; __syncthreads(); }
    float scaleH = ghp[0] / sqrtf(red[0]);

    float4 acc[4];
    acc[0] = acc[1] = acc[2] = acc[3] = make_float4(0.f, 0.f, 0.f, 0.f);
    const float* hx  = g_hx + (b * 32 + x) * 256;
    const float* hyB = g_hy + b * 8192;
    const float* hzB = g_hz + b * 8192;
    for (int c = 0; c < 4; c++) {
        int k0 = c * 64;
        __syncthreads();
        for (int e = tid; e < 2048; e += 128) {
            int kc = e & 63, y = e >> 6;
            st[y * 64 + kc] = hx[k0 + kc] * hyB[y * 256 + k0 + kc];
        }
        for (int e = tid; e < 4096; e += 128) {
            int kc = e & 63, zh = e >> 6;
            sw[kc * 68 + zh] = hzB[(zh >> 1) * 256 + k0 + kc] *
                               Vh[(zh & 1) * 256 + k0 + kc] * scaleH;
        }
        __syncthreads();
        #pragma unroll 4
        for (int kc = 0; kc < 64; kc++) {
            float4 w = *(const float4*)&sw[kc * 68 + zg * 4];
            float t0 = st[(yg*4 + 0) * 64 + kc];
            float t1 = st[(yg*4 + 1) * 64 + kc];
            float t2 = st[(yg*4 + 2) * 64 + kc];
            float t3 = st[(yg*4 + 3) * 64 + kc];
            acc[0].x += t0*w.x; acc[0].y += t0*w.y; acc[0].z += t0*w.z; acc[0].w += t0*w.w;
            acc[1].x += t1*w.x; acc[1].y += t1*w.y; acc[1].z += t1*w.z; acc[1].w += t1*w.w;
            acc[2].x += t2*w.x; acc[2].y += t2*w.y; acc[2].z += t2*w.z; acc[2].w += t2*w.w;
            acc[3].x += t3*w.x; acc[3].y += t3*w.y; acc[3].z += t3*w.z; acc[3].w += t3*w.w;
        }
    }
    float b0 = bhp[0], b1 = bhp[1];
    float m0 = -1e30f, m1 = -1e30f;
    float* r0base = g_attraw + ((b * 2 + 0) * 32 + x) * 1024;
    float* r1base = g_attraw + ((b * 2 + 1) * 32 + x) * 1024;
    int z0 = zg * 2;
    #pragma unroll
    for (int i = 0; i < 4; i++) {
        int y = yg * 4 + i;
        float4 v = acc[i];
        v.x += b0; v.y += b1; v.z += b0; v.w += b1;
        m0 = fmaxf(m0, fmaxf(v.x, v.z));
        m1 = fmaxf(m1, fmaxf(v.y, v.w));
        r0base[y * 32 + z0]     = v.x;   // (h=0, z=z0)
        r1base[y * 32 + z0]     = v.y;   // (h=1, z=z0)
        r0base[y * 32 + z0 + 1] = v.z;   // (h=0, z=z0+1)
        r1base[y * 32 + z0 + 1] = v.w;   // (h=1, z=z0+1)
    }
    // block max, h0 then h1
    __syncthreads();
    red[tid] = m0; __syncthreads();
    for (int s = 64; s > 0; s >>= 1) { if (tid < s) red[tid] = fmaxf(red[tid], red[tid + s]); __syncthreads(); }
    float M0 = red[0]; __syncthreads();
    red[tid] = m1; __syncthreads();
    for (int s = 64; s > 0; s >>= 1) { if (tid < s) red[tid] = fmaxf(red[tid], red[tid + s]); __syncthreads(); }
    float M1 = red[0]; __syncthreads();
    // block Σexp(v−M) from live accumulators
    float s0 = 0.f, s1 = 0.f;
    #pragma unroll
    for (int i = 0; i < 4; i++) {
        float4 v = acc[i];
        s0 += expf(v.x + b0 - M0) + expf(v.z + b0 - M0);
        s1 += expf(v.y + b1 - M1) + expf(v.w + b1 - M1);
    }
    red[tid] = s0; __syncthreads();
    for (int s = 64; s > 0; s >>= 1) { if (tid < s) red[tid] += red[tid + s]; __syncthreads(); }
    float S0 = red[0]; __syncthreads();
    red[tid] = s1; __syncthreads();
    for (int s = 64; s > 0; s >>= 1) { if (tid < s) red[tid] += red[tid + s]; __syncthreads(); }
    if (tid == 0) {
        g_partmax[(b * 2 + 0) * 32 + x] = M0;
        g_partmax[(b * 2 + 1) * 32 + x] = M1;
        g_partsum[(b * 2 + 0) * 32 + x] = S0;
        g_partsum[(b * 2 + 1) * 32 + x] = red[0];
    }
}

// ---------------- K3: fused softmax-finalize + att_out + logits partials ----------------
// grid (32 x, 8 b), 256 threads. Combines the 32 online-softmax partials per (b,h)
// with a warp reduce (redundant per block), exps the raw att, writes att_out,
// builds attsum in shared, then computes part[b,x,k] = Σ_y t[y,k]·(Σ_z as[y,z]·hz[z,k]).
__global__ void __launch_bounds__(256) k_fuse(float* __restrict__ att_out) {
    __shared__ float sa[1024];
    __shared__ float shz[256*36];
    __shared__ float sstat[4];     // M0, inv0, M1, inv1
    int x = blockIdx.x, b = blockIdx.y, tid = threadIdx.x;

    // stage hz transposed [k][z]
    for (int e = tid; e < 8192; e += 256) {
        int k = e & 255, z = e >> 8;
        shz[k * 36 + z] = g_hz[(b * 32 + z) * 256 + k];
    }
    // softmax combine: warp 0 -> h0, warp 1 -> h1
    if (tid < 64) {
        int h = tid >> 5, lane = tid & 31;
        float m = g_partmax[(b * 2 + h) * 32 + lane];
        float s = g_partsum[(b * 2 + h) * 32 + lane];
        float M = m;
        #pragma unroll
        for (int o = 16; o > 0; o >>= 1) M = fmaxf(M, __shfl_xor_sync(0xffffffffu, M, o));
        float se = s * expf(m - M);
        #pragma unroll
        for (int o = 16; o > 0; o >>= 1) se += __shfl_xor_sync(0xffffffffu, se, o);
        if (lane == 0) { sstat[h * 2] = M; sstat[h * 2 + 1] = 1.f / se; }
    }
    __syncthreads();
    float M0 = sstat[0], I0 = sstat[1], M1 = sstat[2], I1 = sstat[3];

    const float* r0 = g_attraw + ((b * 2 + 0) * 32 + x) * 1024;
    const float* r1 = g_attraw + ((b * 2 + 1) * 32 + x) * 1024;
    float* o0 = att_out + ((b * 2 + 0) * 32 + x) * 1024;
    float* o1 = att_out + ((b * 2 + 1) * 32 + x) * 1024;
    #pragma unroll
    for (int i = tid; i < 1024; i += 256) {
        float a0 = expf(r0[i] - M0) * I0;
        float a1 = expf(r1[i] - M1) * I1;
        o0[i] = a0;
        o1[i] = a1;
        sa[i] = a0 + a1;
    }
    __syncthreads();

    float sxk = g_hx[(b * 32 + x) * 256 + tid];
    const float* hyB = g_hy + b * 8192;
    float acc = 0.f;
    for (int y = 0; y < 32; y++) {
        float s = 0.f;
        #pragma unroll
        for (int z = 0; z < 32; z += 4) {
            float4 a4 = *(const float4*)&sa[y * 32 + z];
            float4 h4 = *(const float4*)&shz[tid * 36 + z];
            s += a4.x*h4.x + a4.y*h4.y + a4.z*h4.z + a4.w*h4.w;
        }
        acc += sxk * hyB[y * 256 + tid] * s;
    }
    g_part[(b * 32 + x) * 256 + tid] = acc;
}

// ---------------- K4: reduce partials over x + BatchNorm over batch (fused) ----------------
__global__ void __launch_bounds__(256) k_bn(const float* __restrict__ gamma,
                                            const float* __restrict__ beta,
                                            float* __restrict__ outp) {
    int k = threadIdx.x;
    float l[8];
    float mean = 0.f;
    #pragma unroll
    for (int b = 0; b < 8; b++) {
        float s = 0.f;
        #pragma unroll 8
        for (int x = 0; x < 32; x++) s += g_part[(b * 32 + x) * 256 + k];
        l[b] = s;
        mean += s;
    }
    mean *= 0.125f;
    float var = 0.f;
    #pragma unroll
    for (int b = 0; b < 8; b++) { float d = l[b] - mean; var += d * d; }
    var *= 0.125f;
    float sc = gamma[k] / sqrtf(var + 1e-5f);
    float bt = beta[k];
    #pragma unroll
    for (int b = 0; b < 8; b++) outp[b * 256 + k] = (l[b] - mean) * sc + bt;
}

// ---------------- launch ----------------
extern "C" void kernel_launch(void* const* d_in, const int* in_sizes, int n_in,
                              void* d_out, int out_size) {
    const float* x     = (const float*)d_in[0];
    const float* y     = (const float*)d_in[1];
    const float* z     = (const float*)d_in[2];
    const float* Vx    = (const float*)d_in[3];
    const float* gx    = (const float*)d_in[4];
    const float* bx    = (const float*)d_in[5];
    const float* Vy    = (const float*)d_in[6];
    const float* gy    = (const float*)d_in[7];
    const float* by    = (const float*)d_in[8];
    const float* Vz    = (const float*)d_in[9];
    const float* gz    = (const float*)d_in[10];
    const float* bz    = (const float*)d_in[11];
    const float* Vh    = (const float*)d_in[12];
    const float* gh    = (const float*)d_in[13];
    const float* bh    = (const float*)d_in[14];
    const float* gamma = (const float*)d_in[15];
    const float* beta  = (const float*)d_in[16];

    float* out     = (float*)d_out;          // [8,256]
    float* att_out = out + 2048;             // [8,2,32,32,32]

    k_proj <<<dim3(4, 8, 3), 256>>>(x, y, z, Vx, gx, bx, Vy, gy, by, Vz, gz, bz);
    k_att  <<<dim3(32, 8), 128>>>(Vh, gh, bh);
    k_fuse <<<dim3(32, 8), 256>>>(att_out);
    k_bn   <<<1, 256>>>(gamma, beta, out);
}

// round 7
// speedup vs baseline: 1.3508x; 1.1430x over previous
#include <cuda_runtime.h>

// ---------------- scratch (__device__ globals; no allocation allowed) ----------------
__device__ float g_hx[8*32*256];
__device__ float g_hy[8*32*256];
__device__ float g_hz[8*32*256];
__device__ float g_attraw[8*2*32768];        // pre-softmax logits [b][h][x][y][z]
__device__ float g_partmax[8*2*32];          // per (b,h,x) block max
__device__ float g_partsum[8*2*32];          // per (b,h,x) Σexp(v - localmax)
__device__ float g_part[8*32*256];           // per (b,x) logits partials

// ---------------- K1: projections  h = relu(in @ (g/||V|| * V)^T + b) ----------------
// grid (4 k-quads, 8 b, 3 mats), 256 threads. Norm of V computed redundantly per block
// (primes L2 for the GEMM reads; removes the separate k_scales kernel).
__global__ void __launch_bounds__(256) k_proj(
    const float* __restrict__ xin, const float* __restrict__ yin, const float* __restrict__ zin,
    const float* __restrict__ Vx, const float* __restrict__ gx, const float* __restrict__ bx,
    const float* __restrict__ Vy, const float* __restrict__ gy, const float* __restrict__ by,
    const float* __restrict__ Vz, const float* __restrict__ gz, const float* __restrict__ bz) {
    __shared__ float sIn[32*128];
    __shared__ float sV[64*33];
    __shared__ float red[256];
    int q = blockIdx.x, b = blockIdx.y, m = blockIdx.z;
    const float* in   = (m == 0) ? xin : (m == 1) ? yin : zin;
    const float* V    = (m == 0) ? Vx  : (m == 1) ? Vy  : Vz;
    const float* gp   = (m == 0) ? gx  : (m == 1) ? gy  : gz;
    const float* bias = (m == 0) ? bx  : (m == 1) ? by  : bz;
    float* out        = (m == 0) ? g_hx : (m == 1) ? g_hy : g_hz;
    int tid = threadIdx.x;
    int k0 = q * 64;

    // stage input tile + compute ||V||^2 (redundant per block, L2-hot)
    for (int e = tid; e < 4096; e += 256) sIn[e] = in[b * 4096 + e];
    float ss = 0.f;
    for (int i = tid; i < 32768; i += 256) { float v = V[i]; ss += v * v; }
    red[tid] = ss; __syncthreads();
    for (int s = 128; s > 0; s >>= 1) {
        if (tid < s) red[tid] += red[tid + s];
        __syncthreads();
    }
    float scale = gp[0] / sqrtf(red[0]);

    int kk = tid & 63, rg = tid >> 6, r0 = rg * 8;
    float acc[8] = {0,0,0,0,0,0,0,0};
    for (int dc = 0; dc < 128; dc += 32) {
        __syncthreads();
        for (int e = tid; e < 2048; e += 256) {
            int kr = e >> 5, d = e & 31;
            sV[kr * 33 + d] = V[(k0 + kr) * 128 + dc + d];
        }
        __syncthreads();
        for (int d = 0; d < 32; d += 4) {
            float v0 = sV[kk*33 + d], v1 = sV[kk*33 + d + 1];
            float v2 = sV[kk*33 + d + 2], v3 = sV[kk*33 + d + 3];
            #pragma unroll
            for (int r = 0; r < 8; r++) {
                float4 iv = *(const float4*)&sIn[(r0 + r) * 128 + dc + d];
                acc[r] += iv.x * v0 + iv.y * v1 + iv.z * v2 + iv.w * v3;
            }
        }
    }
    float bb = bias[k0 + kk];
    #pragma unroll
    for (int r = 0; r < 8; r++) {
        float v = acc[r] * scale + bb;
        out[(b * 32 + r0 + r) * 256 + k0 + kk] = v > 0.f ? v : 0.f;
    }
}

// ---------------- K2: att GEMM + per-(b,h,x) softmax partials ----------------
// att[b,h,x,y,z] = Σ_k (hx*hy)[y,k] * (hz*Wh)[zh,k] + bh
// grid (32 x, 8 b), 128 threads, 4y x 4zh register tile.
// Emits raw att, block max M_x AND block Σexp(v−M_x)  (online-softmax partials).
__global__ void __launch_bounds__(128) k_att(const float* __restrict__ Vh,
                                             const float* __restrict__ ghp,
                                             const float* __restrict__ bhp) {
    __shared__ float st[32*64];    // t[y][kc], phase-broadcast reads
    __shared__ float sw[64*68];    // w[kc][zh], padded -> contiguous 128B per phase
    __shared__ float red[128];
    int x = blockIdx.x, b = blockIdx.y;
    int tid = threadIdx.x;
    int yg = tid >> 4, zg = tid & 15;

    // ||Vh|| (512 elements) — redundant per block, trivial
    float ssh = 0.f;
    for (int i = tid; i < 512; i += 128) { float v = Vh[i]; ssh += v * v; }
    red[tid] = ssh; __syncthreads();
    for (int s = 64; s > 0; s >>= 1) { if (tid < s) red[tid] += red[tid + s]; __syncthreads(); }
    float scaleH = ghp[0] / sqrtf(red[0]);

    float4 acc[4];
    acc[0] = acc[1] = acc[2] = acc[3] = make_float4(0.f, 0.f, 0.f, 0.f);
    const float* hx  = g_hx + (b * 32 + x) * 256;
    const float* hyB = g_hy + b * 8192;
    const float* hzB = g_hz + b * 8192;
    for (int c = 0; c < 4; c++) {
        int k0 = c * 64;
        __syncthreads();
        for (int e = tid; e < 2048; e += 128) {
            int kc = e & 63, y = e >> 6;
            st[y * 64 + kc] = hx[k0 + kc] * hyB[y * 256 + k0 + kc];
        }
        for (int e = tid; e < 4096; e += 128) {
            int kc = e & 63, zh = e >> 6;
            sw[kc * 68 + zh] = hzB[(zh >> 1) * 256 + k0 + kc] *
                               Vh[(zh & 1) * 256 + k0 + kc] * scaleH;
        }
        __syncthreads();
        #pragma unroll 4
        for (int kc = 0; kc < 64; kc++) {
            float4 w = *(const float4*)&sw[kc * 68 + zg * 4];
            float t0 = st[(yg*4 + 0) * 64 + kc];
            float t1 = st[(yg*4 + 1) * 64 + kc];
            float t2 = st[(yg*4 + 2) * 64 + kc];
            float t3 = st[(yg*4 + 3) * 64 + kc];
            acc[0].x += t0*w.x; acc[0].y += t0*w.y; acc[0].z += t0*w.z; acc[0].w += t0*w.w;
            acc[1].x += t1*w.x; acc[1].y += t1*w.y; acc[1].z += t1*w.z; acc[1].w += t1*w.w;
            acc[2].x += t2*w.x; acc[2].y += t2*w.y; acc[2].z += t2*w.z; acc[2].w += t2*w.w;
            acc[3].x += t3*w.x; acc[3].y += t3*w.y; acc[3].z += t3*w.z; acc[3].w += t3*w.w;
        }
    }
    float b0 = bhp[0], b1 = bhp[1];
    float m0 = -1e30f, m1 = -1e30f;
    float* r0base = g_attraw + ((b * 2 + 0) * 32 + x) * 1024;
    float* r1base = g_attraw + ((b * 2 + 1) * 32 + x) * 1024;
    int z0 = zg * 2;
    #pragma unroll
    for (int i = 0; i < 4; i++) {
        int y = yg * 4 + i;
        float4 v = acc[i];
        v.x += b0; v.y += b1; v.z += b0; v.w += b1;
        m0 = fmaxf(m0, fmaxf(v.x, v.z));
        m1 = fmaxf(m1, fmaxf(v.y, v.w));
        r0base[y * 32 + z0]     = v.x;   // (h=0, z=z0)
        r1base[y * 32 + z0]     = v.y;   // (h=1, z=z0)
        r0base[y * 32 + z0 + 1] = v.z;   // (h=0, z=z0+1)
        r1base[y * 32 + z0 + 1] = v.w;   // (h=1, z=z0+1)
    }
    // block max, h0 then h1
    __syncthreads();
    red[tid] = m0; __syncthreads();
    for (int s = 64; s > 0; s >>= 1) { if (tid < s) red[tid] = fmaxf(red[tid], red[tid + s]); __syncthreads(); }
    float M0 = red[0]; __syncthreads();
    red[tid] = m1; __syncthreads();
    for (int s = 64; s > 0; s >>= 1) { if (tid < s) red[tid] = fmaxf(red[tid], red[tid + s]); __syncthreads(); }
    float M1 = red[0]; __syncthreads();
    // block Σexp(v−M) from live accumulators
    float s0 = 0.f, s1 = 0.f;
    #pragma unroll
    for (int i = 0; i < 4; i++) {
        float4 v = acc[i];
        s0 += expf(v.x + b0 - M0) + expf(v.z + b0 - M0);
        s1 += expf(v.y + b1 - M1) + expf(v.w + b1 - M1);
    }
    red[tid] = s0; __syncthreads();
    for (int s = 64; s > 0; s >>= 1) { if (tid < s) red[tid] += red[tid + s]; __syncthreads(); }
    float S0 = red[0]; __syncthreads();
    red[tid] = s1; __syncthreads();
    for (int s = 64; s > 0; s >>= 1) { if (tid < s) red[tid] += red[tid + s]; __syncthreads(); }
    if (tid == 0) {
        g_partmax[(b * 2 + 0) * 32 + x] = M0;
        g_partmax[(b * 2 + 1) * 32 + x] = M1;
        g_partsum[(b * 2 + 0) * 32 + x] = S0;
        g_partsum[(b * 2 + 1) * 32 + x] = red[0];
    }
}

// ---------------- K3: fused softmax-finalize + att_out + logits partials ----------------
// grid (32 x, 8 b), 256 threads. Combines the 32 online-softmax partials per (b,h)
// with a warp reduce (redundant per block), exps the raw att, writes att_out,
// builds attsum in shared, then computes part[b,x,k] = Σ_y t[y,k]·(Σ_z as[y,z]·hz[z,k]).
__global__ void __launch_bounds__(256) k_fuse(float* __restrict__ att_out) {
    __shared__ float sa[1024];
    __shared__ float shz[256*36];
    __shared__ float sstat[4];     // M0, inv0, M1, inv1
    int x = blockIdx.x, b = blockIdx.y, tid = threadIdx.x;

    // stage hz transposed [k][z]
    for (int e = tid; e < 8192; e += 256) {
        int k = e & 255, z = e >> 8;
        shz[k * 36 + z] = g_hz[(b * 32 + z) * 256 + k];
    }
    // softmax combine: warp 0 -> h0, warp 1 -> h1
    if (tid < 64) {
        int h = tid >> 5, lane = tid & 31;
        float m = g_partmax[(b * 2 + h) * 32 + lane];
        float s = g_partsum[(b * 2 + h) * 32 + lane];
        float M = m;
        #pragma unroll
        for (int o = 16; o > 0; o >>= 1) M = fmaxf(M, __shfl_xor_sync(0xffffffffu, M, o));
        float se = s * expf(m - M);
        #pragma unroll
        for (int o = 16; o > 0; o >>= 1) se += __shfl_xor_sync(0xffffffffu, se, o);
        if (lane == 0) { sstat[h * 2] = M; sstat[h * 2 + 1] = 1.f / se; }
    }
    __syncthreads();
    float M0 = sstat[0], I0 = sstat[1], M1 = sstat[2], I1 = sstat[3];

    const float* r0 = g_attraw + ((b * 2 + 0) * 32 + x) * 1024;
    const float* r1 = g_attraw + ((b * 2 + 1) * 32 + x) * 1024;
    float* o0 = att_out + ((b * 2 + 0) * 32 + x) * 1024;
    float* o1 = att_out + ((b * 2 + 1) * 32 + x) * 1024;
    #pragma unroll
    for (int i = tid; i < 1024; i += 256) {
        float a0 = expf(r0[i] - M0) * I0;
        float a1 = expf(r1[i] - M1) * I1;
        o0[i] = a0;
        o1[i] = a1;
        sa[i] = a0 + a1;
    }
    __syncthreads();

    float sxk = g_hx[(b * 32 + x) * 256 + tid];
    const float* hyB = g_hy + b * 8192;
    float acc = 0.f;
    for (int y = 0; y < 32; y++) {
        float s = 0.f;
        #pragma unroll
        for (int z = 0; z < 32; z += 4) {
            float4 a4 = *(const float4*)&sa[y * 32 + z];
            float4 h4 = *(const float4*)&shz[tid * 36 + z];
            s += a4.x*h4.x + a4.y*h4.y + a4.z*h4.z + a4.w*h4.w;
        }
        acc += sxk * hyB[y * 256 + tid] * s;
    }
    g_part[(b * 32 + x) * 256 + tid] = acc;
}

// ---------------- K4: reduce partials + BatchNorm — one warp per k column ----------------
// grid 32 blocks x 256 threads (8 warps). Warp w of block g owns k = g*8+w.
// Per b: 32 lanes load part[b, x=lane, k] (8 independent loads -> MLP=8), shfl-reduce.
__global__ void __launch_bounds__(256) k_bn(const float* __restrict__ gamma,
                                            const float* __restrict__ beta,
                                            float* __restrict__ outp) {
    int warp = threadIdx.x >> 5, lane = threadIdx.x & 31;
    int k = blockIdx.x * 8 + warp;
    float l[8];
    #pragma unroll
    for (int b = 0; b < 8; b++) l[b] = g_part[(b * 32 + lane) * 256 + k];
    #pragma unroll
    for (int b = 0; b < 8; b++) {
        float v = l[b];
        #pragma unroll
        for (int o = 16; o > 0; o >>= 1) v += __shfl_xor_sync(0xffffffffu, v, o);
        l[b] = v;                       // every lane holds the full sum
    }
    float mean = 0.f;
    #pragma unroll
    for (int b = 0; b < 8; b++) mean += l[b];
    mean *= 0.125f;
    float var = 0.f;
    #pragma unroll
    for (int b = 0; b < 8; b++) { float d = l[b] - mean; var += d * d; }
    var *= 0.125f;
    float sc = gamma[k] / sqrtf(var + 1e-5f);
    float bt = beta[k];
    if (lane < 8) outp[lane * 256 + k] = (l[lane] - mean) * sc + bt;
}

// ---------------- launch ----------------
extern "C" void kernel_launch(void* const* d_in, const int* in_sizes, int n_in,
                              void* d_out, int out_size) {
    const float* x     = (const float*)d_in[0];
    const float* y     = (const float*)d_in[1];
    const float* z     = (const float*)d_in[2];
    const float* Vx    = (const float*)d_in[3];
    const float* gx    = (const float*)d_in[4];
    const float* bx    = (const float*)d_in[5];
    const float* Vy    = (const float*)d_in[6];
    const float* gy    = (const float*)d_in[7];
    const float* by    = (const float*)d_in[8];
    const float* Vz    = (const float*)d_in[9];
    const float* gz    = (const float*)d_in[10];
    const float* bz    = (const float*)d_in[11];
    const float* Vh    = (const float*)d_in[12];
    const float* gh    = (const float*)d_in[13];
    const float* bh    = (const float*)d_in[14];
    const float* gamma = (const float*)d_in[15];
    const float* beta  = (const float*)d_in[16];

    float* out     = (float*)d_out;          // [8,256]
    float* att_out = out + 2048;             // [8,2,32,32,32]

    k_proj <<<dim3(4, 8, 3), 256>>>(x, y, z, Vx, gx, bx, Vy, gy, by, Vz, gz, bz);
    k_att  <<<dim3(32, 8), 128>>>(Vh, gh, bh);
    k_fuse <<<dim3(32, 8), 256>>>(att_out);
    k_bn   <<<32, 256>>>(gamma, beta, out);
}